// round 15
// baseline (speedup 1.0000x reference)
#include <cuda_runtime.h>
#include <cuda_fp16.h>
#include <cuda_bf16.h>
#include <math.h>

#define NN 100000
#define EG 600000
#define EE 600000

// ---------------- scratch (static device globals; no allocation) ----------------
__device__ __align__(16) __half g_hh[NN * 64];
__device__ __align__(16) __half g_xh[NN * 64];
__device__ float g_out[NN * 64];
__device__ float g_as[NN];
__device__ float g_ad[NN];
__device__ float g_denom[NN];
__device__ float g_alpha[EG];
__device__ __align__(16) __half g_Yh[(size_t)NN * 1040];
__device__ __align__(16) unsigned g_Bl2[64 * 72];     // tf32 [W1 | W1@as | W1@ad | 0]
__device__ __align__(16) unsigned g_Bmlp[64 * 1088];  // tf32 remapped Wm1 (1040 + pad)

__device__ __forceinline__ float fast_elu(float v) {
    return (v > 0.0f) ? v : (__expf(v) - 1.0f);
}

__device__ __forceinline__ unsigned f2tf32(float f) {
    unsigned r; asm("cvt.rna.tf32.f32 %0, %1;" : "=r"(r) : "f"(f)); return r;
}

__device__ __forceinline__ void mma_tf32(float c[4],
                                         unsigned a0, unsigned a1, unsigned a2, unsigned a3,
                                         unsigned b0, unsigned b1) {
    asm volatile("mma.sync.aligned.m16n8k8.row.col.f32.tf32.tf32.f32 "
                 "{%0,%1,%2,%3}, {%4,%5,%6,%7}, {%8,%9}, {%0,%1,%2,%3};"
                 : "+f"(c[0]), "+f"(c[1]), "+f"(c[2]), "+f"(c[3])
                 : "r"(a0), "r"(a1), "r"(a2), "r"(a3), "r"(b0), "r"(b1));
}

// ---------------- one-time B-matrix staging (tiny) ------------------------------
__global__ void prep_B(const float* __restrict__ W1,
                       const float* __restrict__ att_s, const float* __restrict__ att_d,
                       const float* __restrict__ Wm1) {
    int i = blockIdx.x * blockDim.x + threadIdx.x;
    // g_Bl2: 64 rows x 72 cols
    if (i < 64 * 72) {
        int k = i / 72, n = i % 72;
        float v = 0.0f;
        if (n < 64) v = W1[k * 64 + n];
        else if (n == 64 || n == 65) {
            const float* av = (n == 64) ? att_s : att_d;
            float dot = 0.0f;
            for (int c2 = 0; c2 < 64; c2++) dot = fmaf(W1[k * 64 + c2], av[c2], dot);
            v = dot;
        }
        g_Bl2[i] = f2tf32(v);
    }
    // g_Bmlp: 64 rows x 1088 cols (cols 0..519 src, 520..1039 dst, rest 0)
    int j = i - 64 * 72;
    if (j >= 0 && j < 64 * 1088) {
        int k = j >> 10;      // j / 1088 ... careful: 1088 not power of 2
        k = j / 1088;
        int n = j - k * 1088;
        float b = 0.0f;
        if (n < 520) b = Wm1[k * 520 + n];
        else if (n < 1040) b = Wm1[(64 + k) * 520 + (n - 520)];
        g_Bmlp[j] = f2tf32(b);
    }
}

// ---------------- layer 1: h = pos @ W0 (IN=3, SIMT) ; zero accumulators --------
__global__ void node_transform_l1(const float* __restrict__ xin,
                                  const float* __restrict__ W,
                                  const float* __restrict__ att_s,
                                  const float* __restrict__ att_d) {
    const int IN = 3;
    __shared__ float Ws[IN * 64];
    __shared__ float xs[4][IN];
    __shared__ float red_s[4][2];
    __shared__ float red_d[4][2];
    int tid = threadIdx.x; // 256
    int node0 = blockIdx.x * 4;

    {
        int zn = node0 + (tid >> 6);
        if (zn < NN) g_out[(size_t)zn * 64 + (tid & 63)] = 0.0f;
        if (tid < 4 && node0 + tid < NN) g_denom[node0 + tid] = 0.0f;
    }

    for (int i = tid; i < IN * 64; i += 256) Ws[i] = W[i];
    for (int i = tid; i < 4 * IN; i += 256) {
        int g = i / IN, k = i % IN;
        int n = node0 + g;
        xs[g][k] = (n < NN) ? xin[(size_t)n * IN + k] : 0.0f;
    }
    __syncthreads();
    int c = tid & 63;
    int g = tid >> 6;
    int n = node0 + g;
    float v = 0.0f;
#pragma unroll
    for (int k = 0; k < IN; k++) v = fmaf(xs[g][k], Ws[k * 64 + c], v);
    float ps = v * att_s[c];
    float pd = v * att_d[c];
#pragma unroll
    for (int o = 16; o; o >>= 1) {
        ps += __shfl_down_sync(0xFFFFFFFFu, ps, o);
        pd += __shfl_down_sync(0xFFFFFFFFu, pd, o);
    }
    if ((tid & 31) == 0) { red_s[g][c >> 5] = ps; red_d[g][c >> 5] = pd; }
    if (n < NN) g_hh[(size_t)n * 64 + c] = __float2half(v);
    __syncthreads();
    if (n < NN && c == 0) {
        g_as[n] = red_s[g][0] + red_s[g][1];
        g_ad[n] = red_d[g][0] + red_d[g][1];
    }
}

// ---------------- layer 2: tf32 MMA transform (B from staging) -------------------
#define GST 68
#define BST 76

__global__ void node_mma_l2(const float* __restrict__ bias) {
    __shared__ unsigned As[64 * GST];
    __shared__ unsigned Bs[64 * BST];
    int tid = threadIdx.x; // 128
    int m0 = blockIdx.x * 64;

    // B tile: straight vectorized copy from staging (72 cols -> 18 uint4 per row)
    for (int i = tid; i < 64 * 18; i += 128) {
        int k = i / 18, v4 = i % 18;
        uint4 b = ((const uint4*)(g_Bl2 + k * 72))[v4];
        *(uint4*)&Bs[k * BST + v4 * 4] = b;
    }

    // A: finalize layer-1 (denom, bias, ELU), zero g_out in place
    for (int i = tid; i < 64 * 16; i += 128) {
        int r = i >> 4, v = i & 15;
        int m = m0 + r;
        float4 x = make_float4(0.f, 0.f, 0.f, 0.f);
        if (m < NN) {
            float inv = 1.0f / (g_denom[m] + 1e-16f);
            float4 o = ((const float4*)g_out)[(size_t)m * 16 + v];
            float4 b = ((const float4*)bias)[v];
            x.x = fast_elu(fmaf(o.x, inv, b.x));
            x.y = fast_elu(fmaf(o.y, inv, b.y));
            x.z = fast_elu(fmaf(o.z, inv, b.z));
            x.w = fast_elu(fmaf(o.w, inv, b.w));
            ((float4*)g_out)[(size_t)m * 16 + v] = make_float4(0.f, 0.f, 0.f, 0.f);
        }
        unsigned* dst = &As[r * GST + v * 4];
        dst[0] = f2tf32(x.x); dst[1] = f2tf32(x.y); dst[2] = f2tf32(x.z); dst[3] = f2tf32(x.w);
    }
    __syncthreads();
    if (tid < 64 && m0 + tid < NN) g_denom[m0 + tid] = 0.0f;

    int warp = tid >> 5, lane = tid & 31;
    int wm = warp * 16;
    int g = lane >> 2, t = lane & 3;

    float c[9][4];
#pragma unroll
    for (int ni = 0; ni < 9; ni++)
#pragma unroll
        for (int j = 0; j < 4; j++) c[ni][j] = 0.0f;

#pragma unroll
    for (int k8 = 0; k8 < 8; k8++) {
        int kb = k8 * 8;
        unsigned a0 = As[(wm + g) * GST + kb + t];
        unsigned a1 = As[(wm + g + 8) * GST + kb + t];
        unsigned a2 = As[(wm + g) * GST + kb + t + 4];
        unsigned a3 = As[(wm + g + 8) * GST + kb + t + 4];
#pragma unroll
        for (int ni = 0; ni < 9; ni++) {
            unsigned b0 = Bs[(kb + t) * BST + ni * 8 + g];
            unsigned b1 = Bs[(kb + t + 4) * BST + ni * 8 + g];
            mma_tf32(c[ni], a0, a1, a2, a3, b0, b1);
        }
    }

    int r0 = m0 + wm + g;
    int r1 = r0 + 8;
#pragma unroll
    for (int ni = 0; ni < 8; ni++) {
        int col = ni * 8 + t * 2;
        if (r0 < NN)
            *(__half2*)(g_hh + (size_t)r0 * 64 + col) = __floats2half2_rn(c[ni][0], c[ni][1]);
        if (r1 < NN)
            *(__half2*)(g_hh + (size_t)r1 * 64 + col) = __floats2half2_rn(c[ni][2], c[ni][3]);
    }
    if (t == 0) {
        if (r0 < NN) { g_as[r0] = c[8][0]; g_ad[r0] = c[8][1]; }
        if (r1 < NN) { g_as[r1] = c[8][2]; g_ad[r1] = c[8][3]; }
    }
}

// alpha -> leaky_relu -> exp -> denom
__global__ void edge_attn(const int* __restrict__ gsrc, const int* __restrict__ gdst) {
    int i = blockIdx.x * blockDim.x + threadIdx.x;
    if (i >= EG) return;
    float a = g_as[gsrc[i]] + g_ad[gdst[i]];
    a = (a >= 0.0f) ? a : 0.2f * a;
    float e = __expf(a);
    g_alpha[i] = e;
    atomicAdd(&g_denom[gdst[i]], e);
}

// 8 threads per edge; scatter UNNORMALIZED e*h
__global__ void edge_scatter(const int* __restrict__ gsrc, const int* __restrict__ gdst) {
    long long idx = (long long)blockIdx.x * blockDim.x + threadIdx.x;
    int e = (int)(idx >> 3);
    if (e >= EG) return;
    int l = (int)(idx & 7);
    int s = gsrc[e], d = gdst[e];
    float w = g_alpha[e];
    uint4 hv = ((const uint4*)(g_hh + (size_t)s * 64))[l];
    const __half2* hh = (const __half2*)&hv;
    float2 f0 = __half22float2(hh[0]);
    float2 f1 = __half22float2(hh[1]);
    float2 f2 = __half22float2(hh[2]);
    float2 f3 = __half22float2(hh[3]);
    float* od = g_out + (size_t)d * 64 + 8 * l;
    asm volatile("red.global.add.v4.f32 [%0], {%1,%2,%3,%4};"
                 :: "l"(od), "f"(f0.x * w), "f"(f0.y * w), "f"(f1.x * w), "f"(f1.y * w) : "memory");
    asm volatile("red.global.add.v4.f32 [%0], {%1,%2,%3,%4};"
                 :: "l"(od + 4), "f"(f2.x * w), "f"(f2.y * w), "f"(f3.x * w), "f"(f3.y * w) : "memory");
}

// finalize layer 2 to fp16: x = elu(g_out/denom + b1)
__global__ void finalize_node_h(const float* __restrict__ bias) {
    int i = blockIdx.x * blockDim.x + threadIdx.x;
    if (i >= NN * 16) return;
    float inv = 1.0f / (g_denom[i >> 4] + 1e-16f);
    float4 o = ((const float4*)g_out)[i];
    float4 b = ((const float4*)bias)[i & 15];
    __half2 h01 = __floats2half2_rn(fast_elu(fmaf(o.x, inv, b.x)), fast_elu(fmaf(o.y, inv, b.y)));
    __half2 h23 = __floats2half2_rn(fast_elu(fmaf(o.z, inv, b.z)), fast_elu(fmaf(o.w, inv, b.w)));
    uint2 pk;
    pk.x = *(unsigned*)&h01;
    pk.y = *(unsigned*)&h23;
    ((uint2*)g_xh)[i] = pk;
}

// ---------------- tf32 GEMM: Y = x @ B (B from staging) -------------------------
__global__ void gemm_y_tc() {
    __shared__ unsigned As[64 * GST];
    __shared__ unsigned Bs[64 * GST];
    int bm = blockIdx.y, bn = blockIdx.x;
    int tid = threadIdx.x; // 256
    int m0 = bm * 64, n0 = bn * 64;

    for (int i = tid; i < 64 * 8; i += 256) {
        int r = i >> 3, v = i & 7;
        int m = m0 + r;
        unsigned* dst = &As[r * GST + v * 8];
        if (m < NN) {
            uint4 hv = ((const uint4*)(g_xh + (size_t)m * 64))[v];
            const __half2* hh = (const __half2*)&hv;
#pragma unroll
            for (int j = 0; j < 4; j++) {
                float2 f = __half22float2(hh[j]);
                dst[2 * j]     = f2tf32(f.x);
                dst[2 * j + 1] = f2tf32(f.y);
            }
        } else {
#pragma unroll
            for (int j = 0; j < 8; j++) dst[j] = 0u;
        }
    }
    // B tile: vectorized copy from staging (16 uint4 per row)
    for (int i = tid; i < 64 * 16; i += 256) {
        int k = i >> 4, v4 = i & 15;
        uint4 b = ((const uint4*)(g_Bmlp + k * 1088 + n0))[v4];
        *(uint4*)&Bs[k * GST + v4 * 4] = b;
    }
    __syncthreads();

    int warp = tid >> 5, lane = tid & 31;
    int wm = (warp >> 1) * 16;
    int wn = (warp & 1) * 32;
    int g = lane >> 2, t = lane & 3;

    float c[4][4];
#pragma unroll
    for (int ni = 0; ni < 4; ni++)
#pragma unroll
        for (int j = 0; j < 4; j++) c[ni][j] = 0.0f;

#pragma unroll
    for (int k8 = 0; k8 < 8; k8++) {
        int kb = k8 * 8;
        unsigned a0 = As[(wm + g) * GST + kb + t];
        unsigned a1 = As[(wm + g + 8) * GST + kb + t];
        unsigned a2 = As[(wm + g) * GST + kb + t + 4];
        unsigned a3 = As[(wm + g + 8) * GST + kb + t + 4];
#pragma unroll
        for (int ni = 0; ni < 4; ni++) {
            int nb = wn + ni * 8;
            unsigned b0 = Bs[(kb + t) * GST + nb + g];
            unsigned b1 = Bs[(kb + t + 4) * GST + nb + g];
            mma_tf32(c[ni], a0, a1, a2, a3, b0, b1);
        }
    }

#pragma unroll
    for (int ni = 0; ni < 4; ni++) {
        int col = n0 + wn + ni * 8 + t * 2;
        if (col >= 1040) continue;
        int r0 = m0 + wm + g;
        int r1 = r0 + 8;
        if (r0 < NN)
            *(__half2*)(g_Yh + (size_t)r0 * 1040 + col) = __floats2half2_rn(c[ni][0], c[ni][1]);
        if (r1 < NN)
            *(__half2*)(g_Yh + (size_t)r1 * 1040 + col) = __floats2half2_rn(c[ni][2], c[ni][3]);
    }
}

// warp per prediction edge; packed fp16 tables, one LDS.128 per (j,k)
__global__ void edge_mlp(const int* __restrict__ esrc, const int* __restrict__ edst,
                         const float* __restrict__ ea,
                         const float* __restrict__ Wm1, const float* __restrict__ bm1,
                         const float* __restrict__ Wm2, const float* __restrict__ bm2,
                         float* __restrict__ out) {
    __shared__ __align__(16) __half sT[4 * 65 * 8];
    int tid = threadIdx.x; // 256
    for (int i = tid; i < 520; i += 256) {
        int k = i >> 3, j = (i & 7) >> 1, par = i & 1;
        int base = (j * 65 + k) * 8 + par;
        sT[base + 0] = __float2half(bm1[i]);
        sT[base + 2] = __float2half(Wm1[128 * 520 + i]);
        sT[base + 4] = __float2half(Wm1[129 * 520 + i]);
        sT[base + 6] = __float2half(Wm2[i]);
    }
    __syncthreads();
    const uint4* sTv = (const uint4*)sT;
    int e = (blockIdx.x * 256 + tid) >> 5;
    if (e >= EE) return;
    int lane = tid & 31;
    int s = esrc[e], d = edst[e];
    float a0 = ea[2 * e], a1 = ea[2 * e + 1];
    const __half* ysrow = g_Yh + (size_t)s * 1040;
    const __half* ydrow = g_Yh + (size_t)d * 1040 + 520;
    const uint4* ys = (const uint4*)ysrow;
    const uint4* yd = (const uint4*)ydrow;
    float acc = 0.0f;
#pragma unroll
    for (int it = 0; it < 2; it++) {
        int k = lane + it * 32;
        uint4 va = ys[k];
        uint4 vb = yd[k];
        const __half2* ha = (const __half2*)&va;
        const __half2* hb = (const __half2*)&vb;
#pragma unroll
        for (int j = 0; j < 4; j++) {
            uint4 tv = sTv[j * 65 + k];
            const __half2* th = (const __half2*)&tv;
            float2 fs = __half22float2(__hadd2(ha[j], hb[j]));
            float2 Bf  = __half22float2(th[0]);
            float2 C0f = __half22float2(th[1]);
            float2 C1f = __half22float2(th[2]);
            float2 W2f = __half22float2(th[3]);
            float v0 = fmaf(a1, C1f.x, fmaf(a0, C0f.x, fs.x + Bf.x));
            float v1 = fmaf(a1, C1f.y, fmaf(a0, C0f.y, fs.y + Bf.y));
            acc = fmaf(fast_elu(v0), W2f.x, acc);
            acc = fmaf(fast_elu(v1), W2f.y, acc);
        }
    }
    if (lane < 4) {
        int ci = 512 + lane * 2;
        uint4 tv = sTv[lane * 65 + 64];
        const __half2* th = (const __half2*)&tv;
        float2 fs = __half22float2(__hadd2(*(const __half2*)(ysrow + ci),
                                           *(const __half2*)(ydrow + ci)));
        float2 Bf  = __half22float2(th[0]);
        float2 C0f = __half22float2(th[1]);
        float2 C1f = __half22float2(th[2]);
        float2 W2f = __half22float2(th[3]);
        float v0 = fmaf(a1, C1f.x, fmaf(a0, C0f.x, fs.x + Bf.x));
        float v1 = fmaf(a1, C1f.y, fmaf(a0, C0f.y, fs.y + Bf.y));
        acc = fmaf(fast_elu(v0), W2f.x, acc);
        acc = fmaf(fast_elu(v1), W2f.y, acc);
    }
#pragma unroll
    for (int o = 16; o; o >>= 1) acc += __shfl_down_sync(0xFFFFFFFFu, acc, o);
    if (lane == 0) out[e] = acc + bm2[0];
}

extern "C" void kernel_launch(void* const* d_in, const int* in_sizes, int n_in,
                              void* d_out, int out_size) {
    const float* pos   = (const float*)d_in[0];
    const int*   eidx  = (const int*)d_in[1];
    const int*   geidx = (const int*)d_in[2];
    const float* eattr = (const float*)d_in[3];
    const float* W0    = (const float*)d_in[4];
    const float* as0   = (const float*)d_in[5];
    const float* ad0   = (const float*)d_in[6];
    const float* b0    = (const float*)d_in[7];
    const float* W1    = (const float*)d_in[8];
    const float* as1   = (const float*)d_in[9];
    const float* ad1   = (const float*)d_in[10];
    const float* b1    = (const float*)d_in[11];
    const float* Wm1   = (const float*)d_in[12];
    const float* bm1   = (const float*)d_in[13];
    const float* Wm2   = (const float*)d_in[14];
    const float* bm2   = (const float*)d_in[15];
    float* out = (float*)d_out;

    const int* gsrc = geidx;
    const int* gdst = geidx + EG;
    const int* esrc = eidx;
    const int* edst = eidx + EE;

    // stage both B matrices (runs concurrently with layer-1 work on the GPU)
    int prep_total = 64 * 72 + 64 * 1088;
    prep_B<<<(prep_total + 255) / 256, 256>>>(W1, as1, ad1, Wm1);

    // layer 1
    node_transform_l1<<<(NN + 3) / 4, 256>>>(pos, W0, as0, ad0);
    edge_attn<<<(EG + 255) / 256, 256>>>(gsrc, gdst);
    edge_scatter<<<((long long)EG * 8 + 255) / 256, 256>>>(gsrc, gdst);
    // layer 2: MMA transform (fused layer-1 finalize, folded attention)
    node_mma_l2<<<(NN + 63) / 64, 128>>>(b0);
    edge_attn<<<(EG + 255) / 256, 256>>>(gsrc, gdst);
    edge_scatter<<<((long long)EG * 8 + 255) / 256, 256>>>(gsrc, gdst);
    // finalize layer 2 to fp16, then GEMM
    finalize_node_h<<<(NN * 16 + 255) / 256, 256>>>(b1);
    dim3 ggrid(17, (NN + 63) / 64);
    gemm_y_tc<<<ggrid, 256>>>();
    // per-edge MLP
    edge_mlp<<<((long long)EE * 32 + 255) / 256, 256>>>(esrc, edst, eattr, Wm1, bm1, Wm2, bm2, out);
}

// round 16
// speedup vs baseline: 1.4505x; 1.4505x over previous
#include <cuda_runtime.h>
#include <cuda_fp16.h>
#include <cuda_bf16.h>
#include <math.h>

#define NN 100000
#define EG 600000
#define EE 600000

// ---------------- scratch (static device globals; no allocation) ----------------
__device__ __align__(16) __half g_hh[NN * 64];   // fp16 h (per-layer transformed feats)
__device__ __align__(16) __half g_xh[NN * 64];   // fp16 finalized layer-2 output
__device__ float g_out[NN * 64];
__device__ float g_as[NN];
__device__ float g_ad[NN];
__device__ float g_denom[NN];
__device__ float g_alpha[EG];
__device__ __align__(16) __half g_Yh[(size_t)NN * 1040];
__device__ __align__(16) unsigned g_Bl2[64 * 72]; // tf32 [W1 | W1@att_s | W1@att_d | 0]

__device__ __forceinline__ float fast_elu(float v) {
    return (v > 0.0f) ? v : (__expf(v) - 1.0f);
}

__device__ __forceinline__ unsigned f2tf32(float f) {
    unsigned r; asm("cvt.rna.tf32.f32 %0, %1;" : "=r"(r) : "f"(f)); return r;
}

__device__ __forceinline__ void mma_tf32(float c[4],
                                         unsigned a0, unsigned a1, unsigned a2, unsigned a3,
                                         unsigned b0, unsigned b1) {
    asm volatile("mma.sync.aligned.m16n8k8.row.col.f32.tf32.tf32.f32 "
                 "{%0,%1,%2,%3}, {%4,%5,%6,%7}, {%8,%9}, {%0,%1,%2,%3};"
                 : "+f"(c[0]), "+f"(c[1]), "+f"(c[2]), "+f"(c[3])
                 : "r"(a0), "r"(a1), "r"(a2), "r"(a3), "r"(b0), "r"(b1));
}

// ---------------- one-time staging of the layer-2 B matrix (18 KB) --------------
__global__ void prep_Bl2(const float* __restrict__ W1,
                         const float* __restrict__ att_s, const float* __restrict__ att_d) {
    int i = blockIdx.x * blockDim.x + threadIdx.x;
    if (i >= 64 * 72) return;
    int k = i / 72, n = i % 72;
    float v = 0.0f;
    if (n < 64) v = W1[k * 64 + n];
    else if (n == 64 || n == 65) {
        const float* av = (n == 64) ? att_s : att_d;
        float dot = 0.0f;
        for (int c2 = 0; c2 < 64; c2++) dot = fmaf(W1[k * 64 + c2], av[c2], dot);
        v = dot;
    }
    g_Bl2[i] = f2tf32(v);
}

// ---------------- layer 1: h = pos @ W0 (IN=3, SIMT) ; zero accumulators --------
__global__ void node_transform_l1(const float* __restrict__ xin,
                                  const float* __restrict__ W,
                                  const float* __restrict__ att_s,
                                  const float* __restrict__ att_d) {
    const int IN = 3;
    __shared__ float Ws[IN * 64];
    __shared__ float xs[4][IN];
    __shared__ float red_s[4][2];
    __shared__ float red_d[4][2];
    int tid = threadIdx.x; // 256
    int node0 = blockIdx.x * 4;

    {
        int zn = node0 + (tid >> 6);
        if (zn < NN) g_out[(size_t)zn * 64 + (tid & 63)] = 0.0f;
        if (tid < 4 && node0 + tid < NN) g_denom[node0 + tid] = 0.0f;
    }

    for (int i = tid; i < IN * 64; i += 256) Ws[i] = W[i];
    for (int i = tid; i < 4 * IN; i += 256) {
        int g = i / IN, k = i % IN;
        int n = node0 + g;
        xs[g][k] = (n < NN) ? xin[(size_t)n * IN + k] : 0.0f;
    }
    __syncthreads();
    int c = tid & 63;
    int g = tid >> 6;
    int n = node0 + g;
    float v = 0.0f;
#pragma unroll
    for (int k = 0; k < IN; k++) v = fmaf(xs[g][k], Ws[k * 64 + c], v);
    float ps = v * att_s[c];
    float pd = v * att_d[c];
#pragma unroll
    for (int o = 16; o; o >>= 1) {
        ps += __shfl_down_sync(0xFFFFFFFFu, ps, o);
        pd += __shfl_down_sync(0xFFFFFFFFu, pd, o);
    }
    if ((tid & 31) == 0) { red_s[g][c >> 5] = ps; red_d[g][c >> 5] = pd; }
    if (n < NN) g_hh[(size_t)n * 64 + c] = __float2half(v);
    __syncthreads();
    if (n < NN && c == 0) {
        g_as[n] = red_s[g][0] + red_s[g][1];
        g_ad[n] = red_d[g][0] + red_d[g][1];
    }
}

// ---------------- layer 2: tf32 MMA transform (B from 18 KB staging) -------------
// x = elu(g_out/denom + b0)  (finalize of layer 1, inline in A load)
// [h | as | ad] = x @ g_Bl2. Also zeroes g_out / g_denom for layer 2's scatter.
#define GST 68
#define BST 76

__global__ void node_mma_l2(const float* __restrict__ bias) {
    __shared__ unsigned As[64 * GST];   // 64 rows x 64 K
    __shared__ unsigned Bs[64 * BST];   // 64 K x 72 N (+pad)
    int tid = threadIdx.x; // 128
    int m0 = blockIdx.x * 64;

    // B tile: vectorized copy from staging (18 uint4 per row, L2-hot)
    for (int i = tid; i < 64 * 18; i += 128) {
        int k = i / 18, v4 = i % 18;
        uint4 b = ((const uint4*)(g_Bl2 + k * 72))[v4];
        *(uint4*)&Bs[k * BST + v4 * 4] = b;
    }

    // A: finalize layer-1 (denom, bias, ELU), zero g_out in place
    for (int i = tid; i < 64 * 16; i += 128) {
        int r = i >> 4, v = i & 15;
        int m = m0 + r;
        float4 x = make_float4(0.f, 0.f, 0.f, 0.f);
        if (m < NN) {
            float inv = 1.0f / (g_denom[m] + 1e-16f);
            float4 o = ((const float4*)g_out)[(size_t)m * 16 + v];
            float4 b = ((const float4*)bias)[v];
            x.x = fast_elu(fmaf(o.x, inv, b.x));
            x.y = fast_elu(fmaf(o.y, inv, b.y));
            x.z = fast_elu(fmaf(o.z, inv, b.z));
            x.w = fast_elu(fmaf(o.w, inv, b.w));
            ((float4*)g_out)[(size_t)m * 16 + v] = make_float4(0.f, 0.f, 0.f, 0.f);
        }
        unsigned* dst = &As[r * GST + v * 4];
        dst[0] = f2tf32(x.x); dst[1] = f2tf32(x.y); dst[2] = f2tf32(x.z); dst[3] = f2tf32(x.w);
    }
    __syncthreads();
    if (tid < 64 && m0 + tid < NN) g_denom[m0 + tid] = 0.0f;  // all denom reads done

    int warp = tid >> 5, lane = tid & 31;
    int wm = warp * 16;               // 4 warps x 16 rows = 64
    int g = lane >> 2, t = lane & 3;

    float c[9][4];
#pragma unroll
    for (int ni = 0; ni < 9; ni++)
#pragma unroll
        for (int j = 0; j < 4; j++) c[ni][j] = 0.0f;

#pragma unroll
    for (int k8 = 0; k8 < 8; k8++) {
        int kb = k8 * 8;
        unsigned a0 = As[(wm + g) * GST + kb + t];
        unsigned a1 = As[(wm + g + 8) * GST + kb + t];
        unsigned a2 = As[(wm + g) * GST + kb + t + 4];
        unsigned a3 = As[(wm + g + 8) * GST + kb + t + 4];
#pragma unroll
        for (int ni = 0; ni < 9; ni++) {
            unsigned b0 = Bs[(kb + t) * BST + ni * 8 + g];
            unsigned b1 = Bs[(kb + t + 4) * BST + ni * 8 + g];
            mma_tf32(c[ni], a0, a1, a2, a3, b0, b1);
        }
    }

    int r0 = m0 + wm + g;
    int r1 = r0 + 8;
#pragma unroll
    for (int ni = 0; ni < 8; ni++) {
        int col = ni * 8 + t * 2;
        if (r0 < NN)
            *(__half2*)(g_hh + (size_t)r0 * 64 + col) = __floats2half2_rn(c[ni][0], c[ni][1]);
        if (r1 < NN)
            *(__half2*)(g_hh + (size_t)r1 * 64 + col) = __floats2half2_rn(c[ni][2], c[ni][3]);
    }
    if (t == 0) {   // cols 64 (as), 65 (ad)
        if (r0 < NN) { g_as[r0] = c[8][0]; g_ad[r0] = c[8][1]; }
        if (r1 < NN) { g_as[r1] = c[8][2]; g_ad[r1] = c[8][3]; }
    }
}

// alpha -> leaky_relu -> exp (softmax max-shift cancels exactly) -> denom
__global__ void edge_attn(const int* __restrict__ gsrc, const int* __restrict__ gdst) {
    int i = blockIdx.x * blockDim.x + threadIdx.x;
    if (i >= EG) return;
    float a = g_as[gsrc[i]] + g_ad[gdst[i]];
    a = (a >= 0.0f) ? a : 0.2f * a;
    float e = __expf(a);
    g_alpha[i] = e;
    atomicAdd(&g_denom[gdst[i]], e);
}

// 8 threads per edge; scatter UNNORMALIZED e*h (normalization deferred)
__global__ void edge_scatter(const int* __restrict__ gsrc, const int* __restrict__ gdst) {
    long long idx = (long long)blockIdx.x * blockDim.x + threadIdx.x;
    int e = (int)(idx >> 3);
    if (e >= EG) return;
    int l = (int)(idx & 7);
    int s = gsrc[e], d = gdst[e];
    float w = g_alpha[e];
    uint4 hv = ((const uint4*)(g_hh + (size_t)s * 64))[l];
    const __half2* hh = (const __half2*)&hv;
    float2 f0 = __half22float2(hh[0]);
    float2 f1 = __half22float2(hh[1]);
    float2 f2 = __half22float2(hh[2]);
    float2 f3 = __half22float2(hh[3]);
    float* od = g_out + (size_t)d * 64 + 8 * l;
    asm volatile("red.global.add.v4.f32 [%0], {%1,%2,%3,%4};"
                 :: "l"(od), "f"(f0.x * w), "f"(f0.y * w), "f"(f1.x * w), "f"(f1.y * w) : "memory");
    asm volatile("red.global.add.v4.f32 [%0], {%1,%2,%3,%4};"
                 :: "l"(od + 4), "f"(f2.x * w), "f"(f2.y * w), "f"(f3.x * w), "f"(f3.y * w) : "memory");
}

// finalize layer 2 to fp16: x = elu(g_out/denom + b1)
__global__ void finalize_node_h(const float* __restrict__ bias) {
    int i = blockIdx.x * blockDim.x + threadIdx.x;
    if (i >= NN * 16) return;
    float inv = 1.0f / (g_denom[i >> 4] + 1e-16f);
    float4 o = ((const float4*)g_out)[i];
    float4 b = ((const float4*)bias)[i & 15];
    __half2 h01 = __floats2half2_rn(fast_elu(fmaf(o.x, inv, b.x)), fast_elu(fmaf(o.y, inv, b.y)));
    __half2 h23 = __floats2half2_rn(fast_elu(fmaf(o.z, inv, b.z)), fast_elu(fmaf(o.w, inv, b.w)));
    uint2 pk;
    pk.x = *(unsigned*)&h01;
    pk.y = *(unsigned*)&h23;
    ((uint2*)g_xh)[i] = pk;
}

// ---------------- tf32 GEMM: Y[N,1040] = x @ B[64,1040] (round-14 form) ---------
__global__ void gemm_y_tc(const float* __restrict__ Wm1) {
    __shared__ unsigned As[64 * GST];
    __shared__ unsigned Bs[64 * GST];
    int bm = blockIdx.y, bn = blockIdx.x;
    int tid = threadIdx.x; // 256
    int m0 = bm * 64, n0 = bn * 64;

    // A tile from fp16 g_xh: 8 uint4 (64 halfs) per row
    for (int i = tid; i < 64 * 8; i += 256) {
        int r = i >> 3, v = i & 7;
        int m = m0 + r;
        unsigned* dst = &As[r * GST + v * 8];
        if (m < NN) {
            uint4 hv = ((const uint4*)(g_xh + (size_t)m * 64))[v];
            const __half2* hh = (const __half2*)&hv;
#pragma unroll
            for (int j = 0; j < 4; j++) {
                float2 f = __half22float2(hh[j]);
                dst[2 * j]     = f2tf32(f.x);
                dst[2 * j + 1] = f2tf32(f.y);
            }
        } else {
#pragma unroll
            for (int j = 0; j < 8; j++) dst[j] = 0u;
        }
    }
    for (int i = tid; i < 64 * 64; i += 256) {
        int k = i >> 6, nl = i & 63;
        int n = n0 + nl;
        float b = 0.0f;
        if (n < 1040) b = (n < 520) ? Wm1[k * 520 + n] : Wm1[(64 + k) * 520 + (n - 520)];
        Bs[k * GST + nl] = f2tf32(b);
    }
    __syncthreads();

    int warp = tid >> 5, lane = tid & 31;
    int wm = (warp >> 1) * 16;
    int wn = (warp & 1) * 32;
    int g = lane >> 2, t = lane & 3;

    float c[4][4];
#pragma unroll
    for (int ni = 0; ni < 4; ni++)
#pragma unroll
        for (int j = 0; j < 4; j++) c[ni][j] = 0.0f;

#pragma unroll
    for (int k8 = 0; k8 < 8; k8++) {
        int kb = k8 * 8;
        unsigned a0 = As[(wm + g) * GST + kb + t];
        unsigned a1 = As[(wm + g + 8) * GST + kb + t];
        unsigned a2 = As[(wm + g) * GST + kb + t + 4];
        unsigned a3 = As[(wm + g + 8) * GST + kb + t + 4];
#pragma unroll
        for (int ni = 0; ni < 4; ni++) {
            int nb = wn + ni * 8;
            unsigned b0 = Bs[(kb + t) * GST + nb + g];
            unsigned b1 = Bs[(kb + t + 4) * GST + nb + g];
            mma_tf32(c[ni], a0, a1, a2, a3, b0, b1);
        }
    }

#pragma unroll
    for (int ni = 0; ni < 4; ni++) {
        int col = n0 + wn + ni * 8 + t * 2;
        if (col >= 1040) continue;
        int r0 = m0 + wm + g;
        int r1 = r0 + 8;
        if (r0 < NN)
            *(__half2*)(g_Yh + (size_t)r0 * 1040 + col) = __floats2half2_rn(c[ni][0], c[ni][1]);
        if (r1 < NN)
            *(__half2*)(g_Yh + (size_t)r1 * 1040 + col) = __floats2half2_rn(c[ni][2], c[ni][3]);
    }
}

// warp per prediction edge; packed fp16 tables, one LDS.128 per (j,k)
__global__ void edge_mlp(const int* __restrict__ esrc, const int* __restrict__ edst,
                         const float* __restrict__ ea,
                         const float* __restrict__ Wm1, const float* __restrict__ bm1,
                         const float* __restrict__ Wm2, const float* __restrict__ bm2,
                         float* __restrict__ out) {
    __shared__ __align__(16) __half sT[4 * 65 * 8];
    int tid = threadIdx.x; // 256
    for (int i = tid; i < 520; i += 256) {
        int k = i >> 3, j = (i & 7) >> 1, par = i & 1;
        int base = (j * 65 + k) * 8 + par;
        sT[base + 0] = __float2half(bm1[i]);
        sT[base + 2] = __float2half(Wm1[128 * 520 + i]);
        sT[base + 4] = __float2half(Wm1[129 * 520 + i]);
        sT[base + 6] = __float2half(Wm2[i]);
    }
    __syncthreads();
    const uint4* sTv = (const uint4*)sT;
    int e = (blockIdx.x * 256 + tid) >> 5;
    if (e >= EE) return;
    int lane = tid & 31;
    int s = esrc[e], d = edst[e];
    float a0 = ea[2 * e], a1 = ea[2 * e + 1];
    const __half* ysrow = g_Yh + (size_t)s * 1040;
    const __half* ydrow = g_Yh + (size_t)d * 1040 + 520;
    const uint4* ys = (const uint4*)ysrow;
    const uint4* yd = (const uint4*)ydrow;
    float acc = 0.0f;
#pragma unroll
    for (int it = 0; it < 2; it++) {
        int k = lane + it * 32;           // 0..63
        uint4 va = ys[k];
        uint4 vb = yd[k];
        const __half2* ha = (const __half2*)&va;
        const __half2* hb = (const __half2*)&vb;
#pragma unroll
        for (int j = 0; j < 4; j++) {
            uint4 tv = sTv[j * 65 + k];
            const __half2* th = (const __half2*)&tv;
            float2 fs = __half22float2(__hadd2(ha[j], hb[j]));
            float2 Bf  = __half22float2(th[0]);
            float2 C0f = __half22float2(th[1]);
            float2 C1f = __half22float2(th[2]);
            float2 W2f = __half22float2(th[3]);
            float v0 = fmaf(a1, C1f.x, fmaf(a0, C0f.x, fs.x + Bf.x));
            float v1 = fmaf(a1, C1f.y, fmaf(a0, C0f.y, fs.y + Bf.y));
            acc = fmaf(fast_elu(v0), W2f.x, acc);
            acc = fmaf(fast_elu(v1), W2f.y, acc);
        }
    }
    if (lane < 4) {                        // tail: channels 512..519 (k=64, j=lane)
        int ci = 512 + lane * 2;
        uint4 tv = sTv[lane * 65 + 64];
        const __half2* th = (const __half2*)&tv;
        float2 fs = __half22float2(__hadd2(*(const __half2*)(ysrow + ci),
                                           *(const __half2*)(ydrow + ci)));
        float2 Bf  = __half22float2(th[0]);
        float2 C0f = __half22float2(th[1]);
        float2 C1f = __half22float2(th[2]);
        float2 W2f = __half22float2(th[3]);
        float v0 = fmaf(a1, C1f.x, fmaf(a0, C0f.x, fs.x + Bf.x));
        float v1 = fmaf(a1, C1f.y, fmaf(a0, C0f.y, fs.y + Bf.y));
        acc = fmaf(fast_elu(v0), W2f.x, acc);
        acc = fmaf(fast_elu(v1), W2f.y, acc);
    }
#pragma unroll
    for (int o = 16; o; o >>= 1) acc += __shfl_down_sync(0xFFFFFFFFu, acc, o);
    if (lane == 0) out[e] = acc + bm2[0];
}

extern "C" void kernel_launch(void* const* d_in, const int* in_sizes, int n_in,
                              void* d_out, int out_size) {
    const float* pos   = (const float*)d_in[0];
    const int*   eidx  = (const int*)d_in[1];
    const int*   geidx = (const int*)d_in[2];
    const float* eattr = (const float*)d_in[3];
    const float* W0    = (const float*)d_in[4];
    const float* as0   = (const float*)d_in[5];
    const float* ad0   = (const float*)d_in[6];
    const float* b0    = (const float*)d_in[7];
    const float* W1    = (const float*)d_in[8];
    const float* as1   = (const float*)d_in[9];
    const float* ad1   = (const float*)d_in[10];
    const float* b1    = (const float*)d_in[11];
    const float* Wm1   = (const float*)d_in[12];
    const float* bm1   = (const float*)d_in[13];
    const float* Wm2   = (const float*)d_in[14];
    const float* bm2   = (const float*)d_in[15];
    float* out = (float*)d_out;

    const int* gsrc = geidx;
    const int* gdst = geidx + EG;
    const int* esrc = eidx;
    const int* edst = eidx + EE;

    // stage the layer-2 B matrix once (overlaps with layer-1 work)
    prep_Bl2<<<(64 * 72 + 255) / 256, 256>>>(W1, as1, ad1);

    // layer 1
    node_transform_l1<<<(NN + 3) / 4, 256>>>(pos, W0, as0, ad0);
    edge_attn<<<(EG + 255) / 256, 256>>>(gsrc, gdst);
    edge_scatter<<<((long long)EG * 8 + 255) / 256, 256>>>(gsrc, gdst);
    // layer 2: tensor-core transform (fused layer-1 finalize, folded attention)
    node_mma_l2<<<(NN + 63) / 64, 128>>>(b0);
    edge_attn<<<(EG + 255) / 256, 256>>>(gsrc, gdst);
    edge_scatter<<<((long long)EG * 8 + 255) / 256, 256>>>(gsrc, gdst);
    // finalize layer 2 to fp16, then GEMM
    finalize_node_h<<<(NN * 16 + 255) / 256, 256>>>(b1);
    dim3 ggrid(17, (NN + 63) / 64);
    gemm_y_tc<<<ggrid, 256>>>(Wm1);
    // per-edge MLP
    edge_mlp<<<((long long)EE * 32 + 255) / 256, 256>>>(esrc, edst, eattr, Wm1, bm1, Wm2, bm2, out);
}